// round 2
// baseline (speedup 1.0000x reference)
#include <cuda_runtime.h>
#include <cuda_bf16.h>

#define LGT   16
#define NROWS 4096
#define DCOLS 16000   // CLASSNUM * LGT

__device__ float        g_acc = 0.0f;
__device__ unsigned int g_cnt = 0u;

__global__ __launch_bounds__(256, 8)
void rvsml_loss_kernel(const float* __restrict__ inputs,
                       const float* __restrict__ labels,
                       float* __restrict__ out) {
    const int row = blockIdx.x;
    const int tid = threadIdx.x;

    // ---- Early gather (warp 0): overlap with the streaming loop below ----
    float w = 0.0f, g = 0.0f;
    if (tid < 32) {
        float lv = 0.0f;
        if (tid <= LGT) lv = __ldg(labels + row * (LGT + 1) + tid);
        const int c = (int)__shfl_sync(0xFFFFFFFFu, lv, LGT);
        if (tid < LGT) {
            w = lv;
            g = __ldg(inputs + (size_t)row * DCOLS + c * LGT + tid);
        }
    }

    // ---- Stream the row (read-once: evict-first), sum of squares ----
    const float4* rowp = reinterpret_cast<const float4*>(inputs + (size_t)row * DCOLS);
    float acc = 0.0f;
    int i = tid;
    #pragma unroll 5
    for (int k = 0; k < 15; k++, i += 256) {   // 15 * 256 = 3840 vecs
        float4 v = __ldcs(rowp + i);
        acc = fmaf(v.x, v.x, acc);
        acc = fmaf(v.y, v.y, acc);
        acc = fmaf(v.z, v.z, acc);
        acc = fmaf(v.w, v.w, acc);
    }
    if (tid < 160) {                           // remainder: 4000 - 3840
        float4 v = __ldcs(rowp + 3840 + tid);
        acc = fmaf(v.x, v.x, acc);
        acc = fmaf(v.y, v.y, acc);
        acc = fmaf(v.z, v.z, acc);
        acc = fmaf(v.w, v.w, acc);
    }

    // ---- Block reduce acc -> sq ----
    __shared__ float warp_sums[8];
    #pragma unroll
    for (int off = 16; off > 0; off >>= 1)
        acc += __shfl_xor_sync(0xFFFFFFFFu, acc, off);
    if ((tid & 31) == 0) warp_sums[tid >> 5] = acc;
    __syncthreads();

    if (tid < 32) {
        float v = (tid < 8) ? warp_sums[tid] : 0.0f;
        #pragma unroll
        for (int off = 4; off > 0; off >>= 1)
            v += __shfl_xor_sync(0xFFFFFFFFu, v, off);
        const float sq = __shfl_sync(0xFFFFFFFFu, v, 0);

        // contrib: lanes >= LGT have w == 0 -> contribute 0
        float contrib = w * (sq + 1.0f - 2.0f * g);
        #pragma unroll
        for (int off = 16; off > 0; off >>= 1)
            contrib += __shfl_xor_sync(0xFFFFFFFFu, contrib, off);

        if (tid == 0) {
            atomicAdd(&g_acc, contrib);
            __threadfence();
            const unsigned ticket = atomicAdd(&g_cnt, 1u);
            if (ticket == NROWS - 1) {
                // All 4096 contributions are visible (each CTA fenced before
                // incrementing the counter). Read + reset for the next replay.
                const float total = atomicExch(&g_acc, 0.0f);
                out[0] = total * (1.0f / (float)NROWS);
                g_cnt = 0u;
                __threadfence();
            }
        }
    }
}

extern "C" void kernel_launch(void* const* d_in, const int* in_sizes, int n_in,
                              void* d_out, int out_size) {
    const float* inputs = (const float*)d_in[0];
    const float* labels = (const float*)d_in[1];
    float* out = (float*)d_out;

    rvsml_loss_kernel<<<NROWS, 256>>>(inputs, labels, out);
}

// round 3
// speedup vs baseline: 1.0056x; 1.0056x over previous
#include <cuda_runtime.h>
#include <cuda_bf16.h>

#define LGT   16
#define NROWS 4096
#define DCOLS 16000   // CLASSNUM * LGT

__device__ float        g_acc = 0.0f;
__device__ unsigned int g_cnt = 0u;

__global__ __launch_bounds__(256, 8)
void rvsml_loss_kernel(const float* __restrict__ inputs,
                       const float* __restrict__ labels,
                       float* __restrict__ out) {
    const int row = blockIdx.x;
    const int tid = threadIdx.x;

    // ---- Stream the row, accumulate sum of squares (R1 loop shape) ----
    const float4* rowp = reinterpret_cast<const float4*>(inputs + (size_t)row * DCOLS);
    const int nvec = DCOLS / 4;  // 4000

    float acc = 0.0f;
    #pragma unroll 4
    for (int i = tid; i < nvec; i += 256) {
        float4 v = rowp[i];
        acc = fmaf(v.x, v.x, acc);
        acc = fmaf(v.y, v.y, acc);
        acc = fmaf(v.z, v.z, acc);
        acc = fmaf(v.w, v.w, acc);
    }

    // ---- Block reduce acc -> sq ----
    __shared__ float warp_sums[8];
    __shared__ float sq_sh;

    #pragma unroll
    for (int off = 16; off > 0; off >>= 1)
        acc += __shfl_xor_sync(0xFFFFFFFFu, acc, off);
    if ((tid & 31) == 0) warp_sums[tid >> 5] = acc;
    __syncthreads();

    if (tid < 32) {
        float v = (tid < 8) ? warp_sums[tid] : 0.0f;
        #pragma unroll
        for (int off = 4; off > 0; off >>= 1)
            v += __shfl_xor_sync(0xFFFFFFFFu, v, off);
        if (tid == 0) sq_sh = v;
    }
    __syncthreads();

    // ---- Gather + weighted contribution (warp 0; row is L2-resident) ----
    if (tid < 32) {
        const float sq = sq_sh;
        const float* lab = labels + row * (LGT + 1);
        float contrib = 0.0f;
        if (tid < LGT) {
            const int c = (int)lab[LGT];
            const float w = lab[tid];
            const float g = inputs[(size_t)row * DCOLS + c * LGT + tid];
            contrib = w * (sq + 1.0f - 2.0f * g);
        }
        #pragma unroll
        for (int off = 16; off > 0; off >>= 1)
            contrib += __shfl_xor_sync(0xFFFFFFFFu, contrib, off);

        if (tid == 0) {
            atomicAdd(&g_acc, contrib);
            __threadfence();
            const unsigned ticket = atomicAdd(&g_cnt, 1u);
            if (ticket == NROWS - 1) {
                // All contributions are visible (each CTA fenced before its
                // counter increment). Read + reset for the next graph replay.
                const float total = atomicExch(&g_acc, 0.0f);
                out[0] = total * (1.0f / (float)NROWS);
                g_cnt = 0u;
                __threadfence();
            }
        }
    }
}

extern "C" void kernel_launch(void* const* d_in, const int* in_sizes, int n_in,
                              void* d_out, int out_size) {
    const float* inputs = (const float*)d_in[0];
    const float* labels = (const float*)d_in[1];
    float* out = (float*)d_out;

    rvsml_loss_kernel<<<NROWS, 256>>>(inputs, labels, out);
}